// round 11
// baseline (speedup 1.0000x reference)
#include <cuda_runtime.h>
#include <cuda_bf16.h>
#include <cstdint>

#define BATCH 4
#define DKDIM 128
#define DVDIM 512
#define NQ 4096
#define NM 8192
#define NCHUNK (NM / 64)
#define KL2E (0.08838834764831843f * 1.4426950408889634f)

// Pre-converted bf16 operands (device globals, allocation-guard-safe)
__device__ __nv_bfloat16 g_KT[(size_t)BATCH * NM * DKDIM];   // [b][m][d]
__device__ __nv_bfloat16 g_VT[(size_t)BATCH * DVDIM * NM];   // [b][dv][m]
__device__ int g_valid[BATCH];

static __device__ __forceinline__ void mma16816(float c[4], uint32_t a0, uint32_t a1,
                                                uint32_t a2, uint32_t a3,
                                                uint32_t b0, uint32_t b1) {
    asm volatile(
        "mma.sync.aligned.m16n8k16.row.col.f32.bf16.bf16.f32 "
        "{%0,%1,%2,%3}, {%4,%5,%6,%7}, {%8,%9}, {%0,%1,%2,%3};\n"
        : "+f"(c[0]), "+f"(c[1]), "+f"(c[2]), "+f"(c[3])
        : "r"(a0), "r"(a1), "r"(a2), "r"(a3), "r"(b0), "r"(b1));
}

#define LDSM4(r0, r1, r2, r3, addr)                                          \
    asm volatile(                                                            \
        "ldmatrix.sync.aligned.m8n8.x4.shared.b16 {%0,%1,%2,%3}, [%4];"      \
        : "=r"(r0), "=r"(r1), "=r"(r2), "=r"(r3) : "r"(addr))

static __device__ __forceinline__ float ex2f(float x) {
    float y;
    asm("ex2.approx.ftz.f32 %0, %1;" : "=f"(y) : "f"(x));
    return y;
}

static __device__ __forceinline__ uint32_t bpack(float lo, float hi) {
    __nv_bfloat162 h = __floats2bfloat162_rn(lo, hi);
    return *reinterpret_cast<uint32_t*>(&h);
}

#define CPA16(dst, src) \
    asm volatile("cp.async.ca.shared.global [%0], [%1], 16;\n" :: "r"(dst), "l"(src))
#define CPA_COMMIT() asm volatile("cp.async.commit_group;\n")
#define CPA_WAIT0() asm volatile("cp.async.wait_group 0;\n")

// ---------------- K0a: transpose+convert mkey -> g_KT[b][m][d] ----------------
__global__ void __launch_bounds__(256) convk_kernel(const float* __restrict__ mk) {
    __shared__ float tile[32][33];
    const int b = blockIdx.z;
    const int m0 = blockIdx.x * 32, d0 = blockIdx.y * 32;
    const int tx = threadIdx.x & 31, ty = threadIdx.x >> 5;
    const float* src = mk + ((size_t)b * DKDIM + d0) * NM + m0;
#pragma unroll
    for (int i = ty; i < 32; i += 8) tile[i][tx] = src[(size_t)i * NM + tx];
    __syncthreads();
    __nv_bfloat16* dst = g_KT + ((size_t)b * NM + m0) * DKDIM + d0;
#pragma unroll
    for (int i = ty; i < 32; i += 8)
        dst[(size_t)i * DKDIM + tx] = __float2bfloat16(tile[tx][i]);
}

// ---------------- K0b: convert mval -> g_VT (same layout) ----------------
__global__ void __launch_bounds__(256) convv_kernel(const float* __restrict__ mv) {
    const size_t i = ((size_t)blockIdx.x * 256 + threadIdx.x) * 4;
    float4 v = *(const float4*)&mv[i];
    uint2 pk = make_uint2(bpack(v.x, v.y), bpack(v.z, v.w));
    *(uint2*)&g_VT[i] = pk;
}

// ---------------- K0c: per-batch validity flags ----------------
__global__ void valid_kernel(const uint32_t* __restrict__ qm,
                             const uint32_t* __restrict__ mm) {
    int b = blockIdx.x;
    int aq = 0, am = 0;
    for (int i = threadIdx.x; i < NQ; i += blockDim.x) aq |= (qm[b * NQ + i] != 0);
    for (int i = threadIdx.x; i < NM; i += blockDim.x) am |= (mm[b * NM + i] != 0);
    aq = __syncthreads_or(aq);
    am = __syncthreads_or(am);
    if (threadIdx.x == 0) g_valid[b] = (aq && am) ? 1 : 0;
}

// ------------- smem layout: 2-stage pipeline, 64q x 256dv CTA -------------
#define KSZB (64 * 136 * 2)            // 17408 per stage, pitch 272B
#define VSZB (256 * 72 * 2)            // 36864 per stage, pitch 144B
#define KOFF 0
#define VOFF (2 * KSZB)                // 34816
#define MOFF (VOFF + 2 * VSZB)         // 108544
#define SMEM_TOTAL (MOFF + 2 * 256)    // 109056  -> 2 CTAs/SM

// -------- Fused flash kernel: 4 warps, 2 CTAs/SM for cross-CTA overlap --------
__global__ void __launch_bounds__(128, 2) flash_kernel(
    const float* __restrict__ qkey, const float* __restrict__ qval,
    const uint32_t* __restrict__ qmask, const uint32_t* __restrict__ mmask,
    float* __restrict__ out) {
    extern __shared__ char smem[];
    float* maskf = (float*)(smem + MOFF);
    const uint32_t smem_u32 = (uint32_t)__cvta_generic_to_shared(smem);

    const int tid = threadIdx.x;
    const int lane = tid & 31, warp = tid >> 5;   // 4 warps
    const int g = lane >> 2, t = lane & 3;
    const int qw = warp * 16;
    const int b = blockIdx.z;
    const int qbase = blockIdx.x * 64;
    const int dvbase = blockIdx.y * 256;

    // B-operand ldmatrix lane offsets (16 rows, alternating +16B col)
    const int lrow = (lane >> 4) * 8 + (lane & 7);
    const int lcol = ((lane >> 3) & 1) * 16;
    const uint32_t koff_l = (uint32_t)(lrow * 272 + lcol);
    const uint32_t voff_l = (uint32_t)(lrow * 144 + lcol);

    // Per-warp persistent Q fragments (16 q rows x 128 d) from fp32 global.
    uint32_t aq[8][4];
    {
        const float* qkb = qkey + (size_t)b * DKDIM * NQ;
        const int q0g = qbase + qw + g;
#pragma unroll
        for (int ks = 0; ks < 8; ks++) {
            const int d0 = ks * 16 + 2 * t;
            const float* p0 = qkb + (size_t)d0 * NQ + q0g;
            const float* p8 = p0 + (size_t)8 * NQ;
            aq[ks][0] = bpack(p0[0], p0[NQ]);
            aq[ks][1] = bpack(p0[8], p0[NQ + 8]);
            aq[ks][2] = bpack(p8[0], p8[NQ]);
            aq[ks][3] = bpack(p8[8], p8[NQ + 8]);
        }
    }

    const __nv_bfloat16* ksrc_b = g_KT + (size_t)b * NM * DKDIM;
    const __nv_bfloat16* vsrc_b = g_VT + ((size_t)b * DVDIM + dvbase) * NM;
    const uint32_t* mmb = mmask + b * NM;

#define PREFETCH(ct)                                                           \
    do {                                                                       \
        const int bufi = (ct) & 1;                                             \
        const char* ksrc = (const char*)(ksrc_b + (size_t)(ct) * 64 * DKDIM);  \
        const uint32_t kdst = smem_u32 + KOFF + bufi * KSZB;                   \
        _Pragma("unroll") for (int k = 0; k < 8; k++) {                        \
            int idx = tid + k * 128;                                           \
            int m = idx >> 4, j = idx & 15;                                    \
            CPA16(kdst + m * 272 + j * 16, ksrc + m * 256 + j * 16);           \
        }                                                                      \
        const char* vsrc = (const char*)(vsrc_b + (size_t)(ct) * 64);          \
        const uint32_t vdst = smem_u32 + VOFF + bufi * VSZB;                   \
        _Pragma("unroll") for (int k = 0; k < 16; k++) {                       \
            int idx = tid + k * 128;                                           \
            int dv = idx >> 3, j = idx & 7;                                    \
            CPA16(vdst + dv * 144 + j * 16,                                    \
                  vsrc + (size_t)dv * (NM * 2) + j * 16);                      \
        }                                                                      \
        if (tid < 64)                                                          \
            maskf[bufi * 64 + tid] = (mmb[(ct) * 64 + tid] != 0) ? 1.f : 0.f;  \
    } while (0)

    float l0 = 0.f, l1 = 0.f;
    float oacc[32][4];
#pragma unroll
    for (int j = 0; j < 32; j++)
#pragma unroll
        for (int c = 0; c < 4; c++) oacc[j][c] = 0.f;

    PREFETCH(0);
    CPA_COMMIT();

    for (int ct = 0; ct < NCHUNK; ct++) {
        CPA_WAIT0();        // chunk ct resident
        __syncthreads();    // all warps done reading buf (ct+1)&1 (prev chunk)
        if (ct + 1 < NCHUNK) {
            PREFETCH(ct + 1);
            CPA_COMMIT();
        }

        const int bufi = ct & 1;
        const uint32_t kfb = smem_u32 + KOFF + bufi * KSZB + koff_l;
        const uint32_t vfb = smem_u32 + VOFF + bufi * VSZB + voff_l;
        const float* Mb = maskf + bufi * 64;

        // ---- QK: S[16q x 64m], K fragments via ldmatrix.x4 ----
        float sc[8][4];
#pragma unroll
        for (int j = 0; j < 8; j++)
#pragma unroll
            for (int c = 0; c < 4; c++) sc[j][c] = 0.f;
#pragma unroll
        for (int ks = 0; ks < 8; ks++) {
#pragma unroll
            for (int j = 0; j < 8; j += 2) {
                uint32_t b0a, b1a, b0b, b1b;
                LDSM4(b0a, b1a, b0b, b1b, kfb + j * (8 * 272) + ks * 32);
                mma16816(sc[j], aq[ks][0], aq[ks][1], aq[ks][2], aq[ks][3], b0a, b1a);
                mma16816(sc[j + 1], aq[ks][0], aq[ks][1], aq[ks][2], aq[ks][3], b0b, b1b);
            }
        }

        // ---- softmax numerator: p = exp2(s*KL2E) * mask ----
#pragma unroll
        for (int j = 0; j < 8; j++) {
            const float mf0 = Mb[j * 8 + 2 * t];
            const float mf1 = Mb[j * 8 + 2 * t + 1];
            sc[j][0] = ex2f(sc[j][0] * KL2E) * mf0;
            sc[j][1] = ex2f(sc[j][1] * KL2E) * mf1;
            sc[j][2] = ex2f(sc[j][2] * KL2E) * mf0;
            sc[j][3] = ex2f(sc[j][3] * KL2E) * mf1;
            l0 += sc[j][0] + sc[j][1];
            l1 += sc[j][2] + sc[j][3];
        }

        // ---- PV: O[16q x 256dv] += P * V, V fragments via ldmatrix.x4 ----
#pragma unroll
        for (int jp = 0; jp < 4; jp++) {
            uint32_t a0 = bpack(sc[2 * jp][0], sc[2 * jp][1]);
            uint32_t a1 = bpack(sc[2 * jp][2], sc[2 * jp][3]);
            uint32_t a2 = bpack(sc[2 * jp + 1][0], sc[2 * jp + 1][1]);
            uint32_t a3 = bpack(sc[2 * jp + 1][2], sc[2 * jp + 1][3]);
#pragma unroll
            for (int jv = 0; jv < 32; jv += 2) {
                uint32_t b0a, b1a, b0b, b1b;
                LDSM4(b0a, b1a, b0b, b1b, vfb + jv * (8 * 144) + jp * 32);
                mma16816(oacc[jv], a0, a1, a2, a3, b0a, b1a);
                mma16816(oacc[jv + 1], a0, a1, a2, a3, b0b, b1b);
            }
        }
    }

    // ---- epilogue: reduce l across quad lanes, apply qmask, add qv ----
    l0 += __shfl_xor_sync(0xffffffffu, l0, 1);
    l0 += __shfl_xor_sync(0xffffffffu, l0, 2);
    l1 += __shfl_xor_sync(0xffffffffu, l1, 1);
    l1 += __shfl_xor_sync(0xffffffffu, l1, 2);

    const int q0 = qbase + qw + g;
    const int vb = g_valid[b];
    const float r0 = (vb != 0 && qmask[b * NQ + q0] != 0) ? 1.f / l0 : 0.f;
    const float r1 = (vb != 0 && qmask[b * NQ + q0 + 8] != 0) ? 1.f / l1 : 0.f;

    const float* qvb = qval + (size_t)b * DVDIM * NQ;
    float* ob = out + (size_t)b * DVDIM * NQ;
#pragma unroll
    for (int jv = 0; jv < 32; jv++) {
        const int dv0 = dvbase + jv * 8 + 2 * t;
        const size_t A = (size_t)dv0 * NQ + q0;
        ob[A] = qvb[A] + oacc[jv][0] * r0;
        ob[A + NQ] = qvb[A + NQ] + oacc[jv][1] * r0;
        ob[A + 8] = qvb[A + 8] + oacc[jv][2] * r1;
        ob[A + NQ + 8] = qvb[A + NQ + 8] + oacc[jv][3] * r1;
    }
}

extern "C" void kernel_launch(void* const* d_in, const int* in_sizes, int n_in,
                              void* d_out, int out_size) {
    const float* qkey = (const float*)d_in[0];
    const float* qval = (const float*)d_in[1];
    const uint32_t* qmask = (const uint32_t*)d_in[2];
    const float* mkey = (const float*)d_in[3];
    const float* mval = (const float*)d_in[4];
    const uint32_t* mmask = (const uint32_t*)d_in[5];
    float* out = (float*)d_out;

    static bool attr_set = false;
    if (!attr_set) {
        cudaFuncSetAttribute(flash_kernel,
                             cudaFuncAttributeMaxDynamicSharedMemorySize,
                             SMEM_TOTAL);
        attr_set = true;
    }

    convk_kernel<<<dim3(NM / 32, DKDIM / 32, BATCH), 256>>>(mkey);
    convv_kernel<<<(unsigned)((size_t)BATCH * DVDIM * NM / 4 / 256), 256>>>(mval);
    valid_kernel<<<BATCH, 256>>>(qmask, mmask);
    flash_kernel<<<dim3(NQ / 64, DVDIM / 256, BATCH), 128, SMEM_TOTAL>>>(
        qkey, qval, qmask, mmask, out);
}

// round 13
// speedup vs baseline: 1.1487x; 1.1487x over previous
#include <cuda_runtime.h>
#include <cuda_bf16.h>
#include <cstdint>

#define BATCH 4
#define DKDIM 128
#define DVDIM 512
#define NQ 4096
#define NM 8192
#define NCHUNK (NM / 64)
#define KL2E (0.08838834764831843f * 1.4426950408889634f)

// Pre-converted bf16 operands (device globals, allocation-guard-safe)
__device__ __nv_bfloat16 g_KT[(size_t)BATCH * NM * DKDIM];   // [b][m][d]
__device__ __nv_bfloat16 g_VT[(size_t)BATCH * DVDIM * NM];   // [b][dv][m]
__device__ int g_valid[BATCH];

static __device__ __forceinline__ void mma16816(float c[4], uint32_t a0, uint32_t a1,
                                                uint32_t a2, uint32_t a3,
                                                uint32_t b0, uint32_t b1) {
    asm volatile(
        "mma.sync.aligned.m16n8k16.row.col.f32.bf16.bf16.f32 "
        "{%0,%1,%2,%3}, {%4,%5,%6,%7}, {%8,%9}, {%0,%1,%2,%3};\n"
        : "+f"(c[0]), "+f"(c[1]), "+f"(c[2]), "+f"(c[3])
        : "r"(a0), "r"(a1), "r"(a2), "r"(a3), "r"(b0), "r"(b1));
}

#define LDSM4(r0, r1, r2, r3, addr)                                          \
    asm volatile(                                                            \
        "ldmatrix.sync.aligned.m8n8.x4.shared.b16 {%0,%1,%2,%3}, [%4];"      \
        : "=r"(r0), "=r"(r1), "=r"(r2), "=r"(r3) : "r"(addr))

static __device__ __forceinline__ float ex2f(float x) {
    float y;
    asm("ex2.approx.ftz.f32 %0, %1;" : "=f"(y) : "f"(x));
    return y;
}

static __device__ __forceinline__ uint32_t bpack(float lo, float hi) {
    __nv_bfloat162 h = __floats2bfloat162_rn(lo, hi);
    return *reinterpret_cast<uint32_t*>(&h);
}

#define CPA16(dst, src) \
    asm volatile("cp.async.ca.shared.global [%0], [%1], 16;\n" :: "r"(dst), "l"(src))
#define CPA_COMMIT() asm volatile("cp.async.commit_group;\n")
#define CPA_WAIT0() asm volatile("cp.async.wait_group 0;\n")

// ---------------- K0a: transpose+convert mkey -> g_KT[b][m][d] ----------------
__global__ void __launch_bounds__(256) convk_kernel(const float* __restrict__ mk) {
    __shared__ float tile[32][33];
    const int b = blockIdx.z;
    const int m0 = blockIdx.x * 32, d0 = blockIdx.y * 32;
    const int tx = threadIdx.x & 31, ty = threadIdx.x >> 5;
    const float* src = mk + ((size_t)b * DKDIM + d0) * NM + m0;
#pragma unroll
    for (int i = ty; i < 32; i += 8) tile[i][tx] = src[(size_t)i * NM + tx];
    __syncthreads();
    __nv_bfloat16* dst = g_KT + ((size_t)b * NM + m0) * DKDIM + d0;
#pragma unroll
    for (int i = ty; i < 32; i += 8)
        dst[(size_t)i * DKDIM + tx] = __float2bfloat16(tile[tx][i]);
}

// ---------------- K0b: convert mval -> g_VT (same layout) ----------------
__global__ void __launch_bounds__(256) convv_kernel(const float* __restrict__ mv) {
    const size_t i = ((size_t)blockIdx.x * 256 + threadIdx.x) * 4;
    float4 v = *(const float4*)&mv[i];
    uint2 pk = make_uint2(bpack(v.x, v.y), bpack(v.z, v.w));
    *(uint2*)&g_VT[i] = pk;
}

// ---------------- K0c: per-batch validity flags ----------------
__global__ void valid_kernel(const uint32_t* __restrict__ qm,
                             const uint32_t* __restrict__ mm) {
    int b = blockIdx.x;
    int aq = 0, am = 0;
    for (int i = threadIdx.x; i < NQ; i += blockDim.x) aq |= (qm[b * NQ + i] != 0);
    for (int i = threadIdx.x; i < NM; i += blockDim.x) am |= (mm[b * NM + i] != 0);
    aq = __syncthreads_or(aq);
    am = __syncthreads_or(am);
    if (threadIdx.x == 0) g_valid[b] = (aq && am) ? 1 : 0;
}

// ---------------- smem layout: 4-stage pipeline, dv-slice 256 ----------------
#define KSZB (64 * 136 * 2)            // 17408 per stage, pitch 272B
#define VSZB (256 * 72 * 2)            // 36864 per stage, pitch 144B
#define KOFF 0
#define VOFF (4 * KSZB)                // 69632
#define MOFF (VOFF + 4 * VSZB)         // 217088
#define SMEM_TOTAL (MOFF + 4 * 256)    // 218112

// ------ Fused flash kernel: dv 256, 2 chunks per barrier (pair loop) ------
__global__ void __launch_bounds__(256, 1) flash_kernel(
    const float* __restrict__ qkey, const float* __restrict__ qval,
    const uint32_t* __restrict__ qmask, const uint32_t* __restrict__ mmask,
    float* __restrict__ out) {
    extern __shared__ char smem[];
    float* maskf = (float*)(smem + MOFF);
    const uint32_t smem_u32 = (uint32_t)__cvta_generic_to_shared(smem);

    const int tid = threadIdx.x;
    const int lane = tid & 31, warp = tid >> 5;
    const int g = lane >> 2, t = lane & 3;
    const int qw = warp * 16;
    const int b = blockIdx.z;
    const int qbase = blockIdx.x * 128;
    const int dvbase = blockIdx.y * 256;

    // B-operand ldmatrix lane offsets (16 rows, alternating +16B col)
    const int lrow = (lane >> 4) * 8 + (lane & 7);
    const int lcol = ((lane >> 3) & 1) * 16;
    const uint32_t koff_l = (uint32_t)(lrow * 272 + lcol);
    const uint32_t voff_l = (uint32_t)(lrow * 144 + lcol);

    // Per-warp persistent Q fragments (16 q rows x 128 d) from fp32 global.
    uint32_t aq[8][4];
    {
        const float* qkb = qkey + (size_t)b * DKDIM * NQ;
        const int q0g = qbase + qw + g;
#pragma unroll
        for (int ks = 0; ks < 8; ks++) {
            const int d0 = ks * 16 + 2 * t;
            const float* p0 = qkb + (size_t)d0 * NQ + q0g;
            const float* p8 = p0 + (size_t)8 * NQ;
            aq[ks][0] = bpack(p0[0], p0[NQ]);
            aq[ks][1] = bpack(p0[8], p0[NQ + 8]);
            aq[ks][2] = bpack(p8[0], p8[NQ]);
            aq[ks][3] = bpack(p8[8], p8[NQ + 8]);
        }
    }

    const __nv_bfloat16* ksrc_b = g_KT + (size_t)b * NM * DKDIM;
    const __nv_bfloat16* vsrc_b = g_VT + ((size_t)b * DVDIM + dvbase) * NM;
    const uint32_t* mmb = mmask + b * NM;

#define PREFETCH(ct)                                                           \
    do {                                                                       \
        const int bufi = (ct) & 3;                                             \
        const char* ksrc = (const char*)(ksrc_b + (size_t)(ct) * 64 * DKDIM);  \
        const uint32_t kdst = smem_u32 + KOFF + bufi * KSZB;                   \
        _Pragma("unroll") for (int k = 0; k < 4; k++) {                        \
            int idx = tid + k * 256;                                           \
            int m = idx >> 4, j = idx & 15;                                    \
            CPA16(kdst + m * 272 + j * 16, ksrc + m * 256 + j * 16);           \
        }                                                                      \
        const char* vsrc = (const char*)(vsrc_b + (size_t)(ct) * 64);          \
        const uint32_t vdst = smem_u32 + VOFF + bufi * VSZB;                   \
        _Pragma("unroll") for (int k = 0; k < 8; k++) {                        \
            int idx = tid + k * 256;                                           \
            int dv = idx >> 3, j = idx & 7;                                    \
            CPA16(vdst + dv * 144 + j * 16,                                    \
                  vsrc + (size_t)dv * (NM * 2) + j * 16);                      \
        }                                                                      \
        if (tid < 64)                                                          \
            maskf[bufi * 64 + tid] = (mmb[(ct) * 64 + tid] != 0) ? 1.f : 0.f;  \
    } while (0)

    // ---- one chunk: QK -> exp/pack -> PV (all R9/R10-validated pieces) ----
#define DO_CHUNK(c)                                                               \
    do {                                                                          \
        const int bufi = (c) & 3;                                                 \
        const uint32_t kfb = smem_u32 + KOFF + bufi * KSZB + koff_l;              \
        const uint32_t vfb = smem_u32 + VOFF + bufi * VSZB + voff_l;              \
        const float* Mb = maskf + bufi * 64;                                      \
        float sc[8][4];                                                           \
        _Pragma("unroll") for (int j = 0; j < 8; j++)                             \
            _Pragma("unroll") for (int cc = 0; cc < 4; cc++) sc[j][cc] = 0.f;     \
        _Pragma("unroll") for (int ks = 0; ks < 8; ks++) {                        \
            _Pragma("unroll") for (int j = 0; j < 8; j += 2) {                    \
                uint32_t b0a, b1a, b0b, b1b;                                      \
                LDSM4(b0a, b1a, b0b, b1b, kfb + j * (8 * 272) + ks * 32);         \
                mma16816(sc[j], aq[ks][0], aq[ks][1], aq[ks][2], aq[ks][3],       \
                         b0a, b1a);                                               \
                mma16816(sc[j + 1], aq[ks][0], aq[ks][1], aq[ks][2], aq[ks][3],   \
                         b0b, b1b);                                               \
            }                                                                     \
        }                                                                         \
        uint32_t pp[16];                                                          \
        _Pragma("unroll") for (int j = 0; j < 8; j++) {                           \
            const float mf0 = Mb[j * 8 + 2 * t];                                  \
            const float mf1 = Mb[j * 8 + 2 * t + 1];                              \
            float p0 = ex2f(sc[j][0] * KL2E) * mf0;                               \
            float p1 = ex2f(sc[j][1] * KL2E) * mf1;                               \
            float p2 = ex2f(sc[j][2] * KL2E) * mf0;                               \
            float p3 = ex2f(sc[j][3] * KL2E) * mf1;                               \
            l0 += p0 + p1;                                                        \
            l1 += p2 + p3;                                                        \
            pp[(j >> 1) * 4 + (j & 1) * 2] = bpack(p0, p1);                       \
            pp[(j >> 1) * 4 + (j & 1) * 2 + 1] = bpack(p2, p3);                   \
        }                                                                         \
        _Pragma("unroll") for (int jp = 0; jp < 4; jp++) {                        \
            _Pragma("unroll") for (int jv = 0; jv < 32; jv += 2) {                \
                uint32_t b0a, b1a, b0b, b1b;                                      \
                LDSM4(b0a, b1a, b0b, b1b, vfb + jv * (8 * 144) + jp * 32);        \
                mma16816(oacc[jv], pp[4 * jp], pp[4 * jp + 1], pp[4 * jp + 2],    \
                         pp[4 * jp + 3], b0a, b1a);                               \
                mma16816(oacc[jv + 1], pp[4 * jp], pp[4 * jp + 1],                \
                         pp[4 * jp + 2], pp[4 * jp + 3], b0b, b1b);               \
            }                                                                     \
        }                                                                         \
    } while (0)

    float l0 = 0.f, l1 = 0.f;
    float oacc[32][4];
#pragma unroll
    for (int j = 0; j < 32; j++)
#pragma unroll
        for (int c = 0; c < 4; c++) oacc[j][c] = 0.f;

    // pair-pipelined mainloop: 1 barrier + 1 wait per 2 chunks
    PREFETCH(0);
    PREFETCH(1);
    CPA_COMMIT();

    for (int ct = 0; ct < NCHUNK; ct += 2) {
        CPA_WAIT0();        // pair (ct, ct+1) resident (only pending group)
        __syncthreads();    // all warps done with pair (ct-2, ct-1) buffers
        if (ct + 2 < NCHUNK) {
            PREFETCH(ct + 2);
            PREFETCH(ct + 3);
            CPA_COMMIT();   // writes into pair (ct-2, ct-1) buffers: safe
        }
        DO_CHUNK(ct);
        DO_CHUNK(ct + 1);
    }

    // ---- epilogue: reduce l across quad lanes, apply qmask, add qv ----
    l0 += __shfl_xor_sync(0xffffffffu, l0, 1);
    l0 += __shfl_xor_sync(0xffffffffu, l0, 2);
    l1 += __shfl_xor_sync(0xffffffffu, l1, 1);
    l1 += __shfl_xor_sync(0xffffffffu, l1, 2);

    const int q0 = qbase + qw + g;
    const int vb = g_valid[b];
    const float r0 = (vb != 0 && qmask[b * NQ + q0] != 0) ? 1.f / l0 : 0.f;
    const float r1 = (vb != 0 && qmask[b * NQ + q0 + 8] != 0) ? 1.f / l1 : 0.f;

    const float* qvb = qval + (size_t)b * DVDIM * NQ;
    float* ob = out + (size_t)b * DVDIM * NQ;
#pragma unroll
    for (int jv = 0; jv < 32; jv++) {
        const int dv0 = dvbase + jv * 8 + 2 * t;
        const size_t A = (size_t)dv0 * NQ + q0;
        ob[A] = qvb[A] + oacc[jv][0] * r0;
        ob[A + NQ] = qvb[A + NQ] + oacc[jv][1] * r0;
        ob[A + 8] = qvb[A + 8] + oacc[jv][2] * r1;
        ob[A + NQ + 8] = qvb[A + NQ + 8] + oacc[jv][3] * r1;
    }
}

extern "C" void kernel_launch(void* const* d_in, const int* in_sizes, int n_in,
                              void* d_out, int out_size) {
    const float* qkey = (const float*)d_in[0];
    const float* qval = (const float*)d_in[1];
    const uint32_t* qmask = (const uint32_t*)d_in[2];
    const float* mkey = (const float*)d_in[3];
    const float* mval = (const float*)d_in[4];
    const uint32_t* mmask = (const uint32_t*)d_in[5];
    float* out = (float*)d_out;

    static bool attr_set = false;
    if (!attr_set) {
        cudaFuncSetAttribute(flash_kernel,
                             cudaFuncAttributeMaxDynamicSharedMemorySize,
                             SMEM_TOTAL);
        attr_set = true;
    }

    convk_kernel<<<dim3(NM / 32, DKDIM / 32, BATCH), 256>>>(mkey);
    convv_kernel<<<(unsigned)((size_t)BATCH * DVDIM * NM / 4 / 256), 256>>>(mval);
    valid_kernel<<<BATCH, 256>>>(qmask, mmask);
    flash_kernel<<<dim3(NQ / 128, DVDIM / 256, BATCH), 256, SMEM_TOTAL>>>(
        qkey, qval, qmask, mmask, out);
}

// round 14
// speedup vs baseline: 1.3327x; 1.1602x over previous
#include <cuda_runtime.h>
#include <cuda_bf16.h>
#include <cstdint>

#define BATCH 4
#define DKDIM 128
#define DVDIM 512
#define NQ 4096
#define NM 8192
#define NCHUNK (NM / 64)
#define KL2E (0.08838834764831843f * 1.4426950408889634f)

// Pre-converted bf16 operands (device globals, allocation-guard-safe)
__device__ __nv_bfloat16 g_KT[(size_t)BATCH * NM * DKDIM];   // [b][m][d]
__device__ __nv_bfloat16 g_VT[(size_t)BATCH * DVDIM * NM];   // [b][dv][m]
__device__ int g_valid[BATCH];

static __device__ __forceinline__ void mma16816(float c[4], uint32_t a0, uint32_t a1,
                                                uint32_t a2, uint32_t a3,
                                                uint32_t b0, uint32_t b1) {
    asm volatile(
        "mma.sync.aligned.m16n8k16.row.col.f32.bf16.bf16.f32 "
        "{%0,%1,%2,%3}, {%4,%5,%6,%7}, {%8,%9}, {%0,%1,%2,%3};\n"
        : "+f"(c[0]), "+f"(c[1]), "+f"(c[2]), "+f"(c[3])
        : "r"(a0), "r"(a1), "r"(a2), "r"(a3), "r"(b0), "r"(b1));
}

#define LDSM4(r0, r1, r2, r3, addr)                                          \
    asm volatile(                                                            \
        "ldmatrix.sync.aligned.m8n8.x4.shared.b16 {%0,%1,%2,%3}, [%4];"      \
        : "=r"(r0), "=r"(r1), "=r"(r2), "=r"(r3) : "r"(addr))

static __device__ __forceinline__ float ex2f(float x) {
    float y;
    asm("ex2.approx.ftz.f32 %0, %1;" : "=f"(y) : "f"(x));
    return y;
}

static __device__ __forceinline__ uint32_t bpack(float lo, float hi) {
    __nv_bfloat162 h = __floats2bfloat162_rn(lo, hi);
    return *reinterpret_cast<uint32_t*>(&h);
}

#define CPA16(dst, src) \
    asm volatile("cp.async.ca.shared.global [%0], [%1], 16;\n" :: "r"(dst), "l"(src))
#define CPA_COMMIT() asm volatile("cp.async.commit_group;\n")
#define CPA_WAIT1() asm volatile("cp.async.wait_group 1;\n")

// ---------------- K0a: transpose+convert mkey -> g_KT[b][m][d] ----------------
__global__ void __launch_bounds__(256) convk_kernel(const float* __restrict__ mk) {
    __shared__ float tile[32][33];
    const int b = blockIdx.z;
    const int m0 = blockIdx.x * 32, d0 = blockIdx.y * 32;
    const int tx = threadIdx.x & 31, ty = threadIdx.x >> 5;
    const float* src = mk + ((size_t)b * DKDIM + d0) * NM + m0;
#pragma unroll
    for (int i = ty; i < 32; i += 8) tile[i][tx] = src[(size_t)i * NM + tx];
    __syncthreads();
    __nv_bfloat16* dst = g_KT + ((size_t)b * NM + m0) * DKDIM + d0;
#pragma unroll
    for (int i = ty; i < 32; i += 8)
        dst[(size_t)i * DKDIM + tx] = __float2bfloat16(tile[tx][i]);
}

// ---------------- K0b: convert mval -> g_VT (same layout) ----------------
__global__ void __launch_bounds__(256) convv_kernel(const float* __restrict__ mv) {
    const size_t i = ((size_t)blockIdx.x * 256 + threadIdx.x) * 4;
    float4 v = *(const float4*)&mv[i];
    uint2 pk = make_uint2(bpack(v.x, v.y), bpack(v.z, v.w));
    *(uint2*)&g_VT[i] = pk;
}

// ---------------- K0c: per-batch validity flags ----------------
__global__ void valid_kernel(const uint32_t* __restrict__ qm,
                             const uint32_t* __restrict__ mm) {
    int b = blockIdx.x;
    int aq = 0, am = 0;
    for (int i = threadIdx.x; i < NQ; i += blockDim.x) aq |= (qm[b * NQ + i] != 0);
    for (int i = threadIdx.x; i < NM; i += blockDim.x) am |= (mm[b * NM + i] != 0);
    aq = __syncthreads_or(aq);
    am = __syncthreads_or(am);
    if (threadIdx.x == 0) g_valid[b] = (aq && am) ? 1 : 0;
}

// ---------------- smem layout: 3-stage pipeline, dv-slice 256 ----------------
#define KSZB (64 * 136 * 2)            // 17408 per stage, pitch 272B
#define VSZB (256 * 72 * 2)            // 36864 per stage, pitch 144B
#define KOFF 0
#define VOFF (3 * KSZB)                // 52224
#define MOFF (VOFF + 3 * VSZB)         // 162816
#define SMEM_TOTAL (MOFF + 3 * 256)    // 163584

// ------ Fused flash kernel: dv 256, batched-LDSM compute (R10 loop) ------
__global__ void __launch_bounds__(256) flash_kernel(
    const float* __restrict__ qkey, const float* __restrict__ qval,
    const uint32_t* __restrict__ qmask, const uint32_t* __restrict__ mmask,
    float* __restrict__ out) {
    extern __shared__ char smem[];
    float* maskf = (float*)(smem + MOFF);
    const uint32_t smem_u32 = (uint32_t)__cvta_generic_to_shared(smem);

    const int tid = threadIdx.x;
    const int lane = tid & 31, warp = tid >> 5;
    const int g = lane >> 2, t = lane & 3;
    const int qw = warp * 16;
    const int b = blockIdx.z;
    const int qbase = blockIdx.x * 128;
    const int dvbase = blockIdx.y * 256;

    // B-operand ldmatrix lane offsets (16 rows, alternating +16B col)
    const int lrow = (lane >> 4) * 8 + (lane & 7);
    const int lcol = ((lane >> 3) & 1) * 16;
    const uint32_t koff_l = (uint32_t)(lrow * 272 + lcol);
    const uint32_t voff_l = (uint32_t)(lrow * 144 + lcol);

    // Per-warp persistent Q fragments (16 q rows x 128 d) from fp32 global.
    uint32_t aq[8][4];
    {
        const float* qkb = qkey + (size_t)b * DKDIM * NQ;
        const int q0g = qbase + qw + g;
#pragma unroll
        for (int ks = 0; ks < 8; ks++) {
            const int d0 = ks * 16 + 2 * t;
            const float* p0 = qkb + (size_t)d0 * NQ + q0g;
            const float* p8 = p0 + (size_t)8 * NQ;
            aq[ks][0] = bpack(p0[0], p0[NQ]);
            aq[ks][1] = bpack(p0[8], p0[NQ + 8]);
            aq[ks][2] = bpack(p8[0], p8[NQ]);
            aq[ks][3] = bpack(p8[8], p8[NQ + 8]);
        }
    }

    const __nv_bfloat16* ksrc_b = g_KT + (size_t)b * NM * DKDIM;
    const __nv_bfloat16* vsrc_b = g_VT + ((size_t)b * DVDIM + dvbase) * NM;
    const uint32_t* mmb = mmask + b * NM;

#define PREFETCH(ct)                                                           \
    do {                                                                       \
        const int bufi = (ct) % 3;                                             \
        const char* ksrc = (const char*)(ksrc_b + (size_t)(ct) * 64 * DKDIM);  \
        const uint32_t kdst = smem_u32 + KOFF + bufi * KSZB;                   \
        _Pragma("unroll") for (int k = 0; k < 4; k++) {                        \
            int idx = tid + k * 256;                                           \
            int m = idx >> 4, j = idx & 15;                                    \
            CPA16(kdst + m * 272 + j * 16, ksrc + m * 256 + j * 16);           \
        }                                                                      \
        const char* vsrc = (const char*)(vsrc_b + (size_t)(ct) * 64);          \
        const uint32_t vdst = smem_u32 + VOFF + bufi * VSZB;                   \
        _Pragma("unroll") for (int k = 0; k < 8; k++) {                        \
            int idx = tid + k * 256;                                           \
            int dv = idx >> 3, j = idx & 7;                                    \
            CPA16(vdst + dv * 144 + j * 16,                                    \
                  vsrc + (size_t)dv * (NM * 2) + j * 16);                      \
        }                                                                      \
        if (tid < 64)                                                          \
            maskf[bufi * 64 + tid] = (mmb[(ct) * 64 + tid] != 0) ? 1.f : 0.f;  \
    } while (0)

    float l0 = 0.f, l1 = 0.f;
    float oacc[32][4];
#pragma unroll
    for (int j = 0; j < 32; j++)
#pragma unroll
        for (int c = 0; c < 4; c++) oacc[j][c] = 0.f;

    PREFETCH(0);
    CPA_COMMIT();
    __syncthreads();  // maskf[0] (plain store) visible before first compute
    PREFETCH(1);
    CPA_COMMIT();

    for (int ct = 0; ct < NCHUNK; ct++) {
        CPA_WAIT1();
        __syncthreads();
        if (ct + 2 < NCHUNK) PREFETCH(ct + 2);
        CPA_COMMIT();  // unconditional: uniform group accounting

        const int bufi = ct % 3;
        const uint32_t kfb = smem_u32 + KOFF + bufi * KSZB + koff_l;
        const uint32_t vfb = smem_u32 + VOFF + bufi * VSZB + voff_l;
        const float* Mb = maskf + bufi * 64;

        // ---- QK: per k-step, batch 4 LDSM4 (MLP=4) then 8 MMAs ----
        float sc[8][4];
#pragma unroll
        for (int j = 0; j < 8; j++)
#pragma unroll
            for (int c = 0; c < 4; c++) sc[j][c] = 0.f;
#pragma unroll
        for (int ks = 0; ks < 8; ks++) {
            uint32_t kb[16];
#pragma unroll
            for (int j4 = 0; j4 < 4; j4++)
                LDSM4(kb[4 * j4], kb[4 * j4 + 1], kb[4 * j4 + 2], kb[4 * j4 + 3],
                      kfb + (2 * j4) * (8 * 272) + ks * 32);
#pragma unroll
            for (int j4 = 0; j4 < 4; j4++) {
                mma16816(sc[2 * j4], aq[ks][0], aq[ks][1], aq[ks][2], aq[ks][3],
                         kb[4 * j4], kb[4 * j4 + 1]);
                mma16816(sc[2 * j4 + 1], aq[ks][0], aq[ks][1], aq[ks][2],
                         aq[ks][3], kb[4 * j4 + 2], kb[4 * j4 + 3]);
            }
        }

        // ---- softmax numerator + pack P (sc dies here) ----
        uint32_t pp[16];
#pragma unroll
        for (int j = 0; j < 8; j++) {
            const float mf0 = Mb[j * 8 + 2 * t];
            const float mf1 = Mb[j * 8 + 2 * t + 1];
            float p0 = ex2f(sc[j][0] * KL2E) * mf0;
            float p1 = ex2f(sc[j][1] * KL2E) * mf1;
            float p2 = ex2f(sc[j][2] * KL2E) * mf0;
            float p3 = ex2f(sc[j][3] * KL2E) * mf1;
            l0 += p0 + p1;
            l1 += p2 + p3;
            pp[(j >> 1) * 4 + (j & 1) * 2] = bpack(p0, p1);
            pp[(j >> 1) * 4 + (j & 1) * 2 + 1] = bpack(p2, p3);
        }

        // ---- PV: per (jp, jg), batch 4 LDSM4 (MLP=4) then 8 MMAs ----
#pragma unroll
        for (int jp = 0; jp < 4; jp++) {
#pragma unroll
            for (int jg = 0; jg < 4; jg++) {
                uint32_t vbf[16];
#pragma unroll
                for (int u = 0; u < 4; u++)
                    LDSM4(vbf[4 * u], vbf[4 * u + 1], vbf[4 * u + 2],
                          vbf[4 * u + 3],
                          vfb + (jg * 8 + 2 * u) * (8 * 144) + jp * 32);
#pragma unroll
                for (int u = 0; u < 4; u++) {
                    const int jv = jg * 8 + 2 * u;
                    mma16816(oacc[jv], pp[4 * jp], pp[4 * jp + 1],
                             pp[4 * jp + 2], pp[4 * jp + 3], vbf[4 * u],
                             vbf[4 * u + 1]);
                    mma16816(oacc[jv + 1], pp[4 * jp], pp[4 * jp + 1],
                             pp[4 * jp + 2], pp[4 * jp + 3], vbf[4 * u + 2],
                             vbf[4 * u + 3]);
                }
            }
        }
    }

    // ---- epilogue: reduce l across quad lanes, apply qmask, add qv ----
    l0 += __shfl_xor_sync(0xffffffffu, l0, 1);
    l0 += __shfl_xor_sync(0xffffffffu, l0, 2);
    l1 += __shfl_xor_sync(0xffffffffu, l1, 1);
    l1 += __shfl_xor_sync(0xffffffffu, l1, 2);

    const int q0 = qbase + qw + g;
    const int vb = g_valid[b];
    const float r0 = (vb != 0 && qmask[b * NQ + q0] != 0) ? 1.f / l0 : 0.f;
    const float r1 = (vb != 0 && qmask[b * NQ + q0 + 8] != 0) ? 1.f / l1 : 0.f;

    const float* qvb = qval + (size_t)b * DVDIM * NQ;
    float* ob = out + (size_t)b * DVDIM * NQ;
#pragma unroll
    for (int jv = 0; jv < 32; jv++) {
        const int dv0 = dvbase + jv * 8 + 2 * t;
        const size_t A = (size_t)dv0 * NQ + q0;
        ob[A] = qvb[A] + oacc[jv][0] * r0;
        ob[A + NQ] = qvb[A + NQ] + oacc[jv][1] * r0;
        ob[A + 8] = qvb[A + 8] + oacc[jv][2] * r1;
        ob[A + NQ + 8] = qvb[A + NQ + 8] + oacc[jv][3] * r1;
    }
}

extern "C" void kernel_launch(void* const* d_in, const int* in_sizes, int n_in,
                              void* d_out, int out_size) {
    const float* qkey = (const float*)d_in[0];
    const float* qval = (const float*)d_in[1];
    const uint32_t* qmask = (const uint32_t*)d_in[2];
    const float* mkey = (const float*)d_in[3];
    const float* mval = (const float*)d_in[4];
    const uint32_t* mmask = (const uint32_t*)d_in[5];
    float* out = (float*)d_out;

    static bool attr_set = false;
    if (!attr_set) {
        cudaFuncSetAttribute(flash_kernel,
                             cudaFuncAttributeMaxDynamicSharedMemorySize,
                             SMEM_TOTAL);
        attr_set = true;
    }

    convk_kernel<<<dim3(NM / 32, DKDIM / 32, BATCH), 256>>>(mkey);
    convv_kernel<<<(unsigned)((size_t)BATCH * DVDIM * NM / 4 / 256), 256>>>(mval);
    valid_kernel<<<BATCH, 256>>>(qmask, mmask);
    flash_kernel<<<dim3(NQ / 128, DVDIM / 256, BATCH), 256, SMEM_TOTAL>>>(
        qkey, qval, qmask, mmask, out);
}

// round 15
// speedup vs baseline: 1.3384x; 1.0043x over previous
#include <cuda_runtime.h>
#include <cuda_bf16.h>
#include <cstdint>

#define BATCH 4
#define DKDIM 128
#define DVDIM 512
#define NQ 4096
#define NM 8192
#define NCHUNK (NM / 64)
#define KL2E (0.08838834764831843f * 1.4426950408889634f)

// Pre-converted bf16 operands (device globals, allocation-guard-safe)
__device__ __nv_bfloat16 g_KT[(size_t)BATCH * NM * DKDIM];   // [b][m][d]
__device__ __nv_bfloat16 g_VT[(size_t)BATCH * DVDIM * NM];   // [b][dv][m]
__device__ int g_valid[BATCH];

static __device__ __forceinline__ void mma16816(float c[4], uint32_t a0, uint32_t a1,
                                                uint32_t a2, uint32_t a3,
                                                uint32_t b0, uint32_t b1) {
    asm volatile(
        "mma.sync.aligned.m16n8k16.row.col.f32.bf16.bf16.f32 "
        "{%0,%1,%2,%3}, {%4,%5,%6,%7}, {%8,%9}, {%0,%1,%2,%3};\n"
        : "+f"(c[0]), "+f"(c[1]), "+f"(c[2]), "+f"(c[3])
        : "r"(a0), "r"(a1), "r"(a2), "r"(a3), "r"(b0), "r"(b1));
}

#define LDSM4(r0, r1, r2, r3, addr)                                          \
    asm volatile(                                                            \
        "ldmatrix.sync.aligned.m8n8.x4.shared.b16 {%0,%1,%2,%3}, [%4];"      \
        : "=r"(r0), "=r"(r1), "=r"(r2), "=r"(r3) : "r"(addr))

static __device__ __forceinline__ float ex2f(float x) {
    float y;
    asm("ex2.approx.ftz.f32 %0, %1;" : "=f"(y) : "f"(x));
    return y;
}

static __device__ __forceinline__ uint32_t bpack(float lo, float hi) {
    __nv_bfloat162 h = __floats2bfloat162_rn(lo, hi);
    return *reinterpret_cast<uint32_t*>(&h);
}

#define CPA16(dst, src) \
    asm volatile("cp.async.ca.shared.global [%0], [%1], 16;\n" :: "r"(dst), "l"(src))
#define CPA_COMMIT() asm volatile("cp.async.commit_group;\n")
#define CPA_WAIT1() asm volatile("cp.async.wait_group 1;\n")

// ---------------- K0a: transpose+convert mkey -> g_KT[b][m][d] ----------------
__global__ void __launch_bounds__(256) convk_kernel(const float* __restrict__ mk) {
    __shared__ float tile[32][33];
    const int b = blockIdx.z;
    const int m0 = blockIdx.x * 32, d0 = blockIdx.y * 32;
    const int tx = threadIdx.x & 31, ty = threadIdx.x >> 5;
    const float* src = mk + ((size_t)b * DKDIM + d0) * NM + m0;
#pragma unroll
    for (int i = ty; i < 32; i += 8) tile[i][tx] = src[(size_t)i * NM + tx];
    __syncthreads();
    __nv_bfloat16* dst = g_KT + ((size_t)b * NM + m0) * DKDIM + d0;
#pragma unroll
    for (int i = ty; i < 32; i += 8)
        dst[(size_t)i * DKDIM + tx] = __float2bfloat16(tile[tx][i]);
}

// ---------------- K0b: convert mval -> g_VT (same layout) ----------------
__global__ void __launch_bounds__(256) convv_kernel(const float* __restrict__ mv) {
    const size_t i = ((size_t)blockIdx.x * 256 + threadIdx.x) * 4;
    float4 v = *(const float4*)&mv[i];
    uint2 pk = make_uint2(bpack(v.x, v.y), bpack(v.z, v.w));
    *(uint2*)&g_VT[i] = pk;
}

// ---------------- K0c: per-batch validity flags ----------------
__global__ void valid_kernel(const uint32_t* __restrict__ qm,
                             const uint32_t* __restrict__ mm) {
    int b = blockIdx.x;
    int aq = 0, am = 0;
    for (int i = threadIdx.x; i < NQ; i += blockDim.x) aq |= (qm[b * NQ + i] != 0);
    for (int i = threadIdx.x; i < NM; i += blockDim.x) am |= (mm[b * NM + i] != 0);
    aq = __syncthreads_or(aq);
    am = __syncthreads_or(am);
    if (threadIdx.x == 0) g_valid[b] = (aq && am) ? 1 : 0;
}

// ---------------- smem layout: 3-stage pipeline, dv-slice 256 ----------------
#define KSZB (64 * 136 * 2)            // 17408 per stage, pitch 272B
#define VSZB (256 * 72 * 2)            // 36864 per stage, pitch 144B
#define KOFF 0
#define VOFF (3 * KSZB)                // 52224
#define MOFF (VOFF + 3 * VSZB)         // 162816
#define SMEM_TOTAL (MOFF + 3 * 256)    // 163584

// -- Fused flash kernel: dv 256, batched LDSM, exp interleaved into PV --
__global__ void __launch_bounds__(256) flash_kernel(
    const float* __restrict__ qkey, const float* __restrict__ qval,
    const uint32_t* __restrict__ qmask, const uint32_t* __restrict__ mmask,
    float* __restrict__ out) {
    extern __shared__ char smem[];
    float* maskf = (float*)(smem + MOFF);
    const uint32_t smem_u32 = (uint32_t)__cvta_generic_to_shared(smem);

    const int tid = threadIdx.x;
    const int lane = tid & 31, warp = tid >> 5;
    const int g = lane >> 2, t = lane & 3;
    const int qw = warp * 16;
    const int b = blockIdx.z;
    const int qbase = blockIdx.x * 128;
    const int dvbase = blockIdx.y * 256;

    // B-operand ldmatrix lane offsets (16 rows, alternating +16B col)
    const int lrow = (lane >> 4) * 8 + (lane & 7);
    const int lcol = ((lane >> 3) & 1) * 16;
    const uint32_t koff_l = (uint32_t)(lrow * 272 + lcol);
    const uint32_t voff_l = (uint32_t)(lrow * 144 + lcol);

    // Per-warp persistent Q fragments (16 q rows x 128 d) from fp32 global.
    uint32_t aq[8][4];
    {
        const float* qkb = qkey + (size_t)b * DKDIM * NQ;
        const int q0g = qbase + qw + g;
#pragma unroll
        for (int ks = 0; ks < 8; ks++) {
            const int d0 = ks * 16 + 2 * t;
            const float* p0 = qkb + (size_t)d0 * NQ + q0g;
            const float* p8 = p0 + (size_t)8 * NQ;
            aq[ks][0] = bpack(p0[0], p0[NQ]);
            aq[ks][1] = bpack(p0[8], p0[NQ + 8]);
            aq[ks][2] = bpack(p8[0], p8[NQ]);
            aq[ks][3] = bpack(p8[8], p8[NQ + 8]);
        }
    }

    const __nv_bfloat16* ksrc_b = g_KT + (size_t)b * NM * DKDIM;
    const __nv_bfloat16* vsrc_b = g_VT + ((size_t)b * DVDIM + dvbase) * NM;
    const uint32_t* mmb = mmask + b * NM;

#define PREFETCH(ct)                                                           \
    do {                                                                       \
        const int bufi = (ct) % 3;                                             \
        const char* ksrc = (const char*)(ksrc_b + (size_t)(ct) * 64 * DKDIM);  \
        const uint32_t kdst = smem_u32 + KOFF + bufi * KSZB;                   \
        _Pragma("unroll") for (int k = 0; k < 4; k++) {                        \
            int idx = tid + k * 256;                                           \
            int m = idx >> 4, j = idx & 15;                                    \
            CPA16(kdst + m * 272 + j * 16, ksrc + m * 256 + j * 16);           \
        }                                                                      \
        const char* vsrc = (const char*)(vsrc_b + (size_t)(ct) * 64);          \
        const uint32_t vdst = smem_u32 + VOFF + bufi * VSZB;                   \
        _Pragma("unroll") for (int k = 0; k < 8; k++) {                        \
            int idx = tid + k * 256;                                           \
            int dv = idx >> 3, j = idx & 7;                                    \
            CPA16(vdst + dv * 144 + j * 16,                                    \
                  vsrc + (size_t)dv * (NM * 2) + j * 16);                      \
        }                                                                      \
        if (tid < 64)                                                          \
            maskf[bufi * 64 + tid] =                                           \
                (mmb[(ct) * 64 + tid] != 0) ? 0.f : -1e30f;                    \
    } while (0)

    float l0 = 0.f, l1 = 0.f;
    float oacc[32][4];
#pragma unroll
    for (int j = 0; j < 32; j++)
#pragma unroll
        for (int c = 0; c < 4; c++) oacc[j][c] = 0.f;

    PREFETCH(0);
    CPA_COMMIT();
    __syncthreads();  // maskf[0] (plain store) visible before first compute
    PREFETCH(1);
    CPA_COMMIT();

    for (int ct = 0; ct < NCHUNK; ct++) {
        CPA_WAIT1();
        __syncthreads();
        if (ct + 2 < NCHUNK) PREFETCH(ct + 2);
        CPA_COMMIT();  // unconditional: uniform group accounting

        const int bufi = ct % 3;
        const uint32_t kfb = smem_u32 + KOFF + bufi * KSZB + koff_l;
        const uint32_t vfb = smem_u32 + VOFF + bufi * VSZB + voff_l;
        const float* Mb = maskf + bufi * 64;

        // ---- QK: per k-step, batch 4 LDSM4 (MLP=4) then 8 MMAs ----
        float sc[8][4];
#pragma unroll
        for (int j = 0; j < 8; j++)
#pragma unroll
            for (int c = 0; c < 4; c++) sc[j][c] = 0.f;
#pragma unroll
        for (int ks = 0; ks < 8; ks++) {
            uint32_t kb[16];
#pragma unroll
            for (int j4 = 0; j4 < 4; j4++)
                LDSM4(kb[4 * j4], kb[4 * j4 + 1], kb[4 * j4 + 2], kb[4 * j4 + 3],
                      kfb + (2 * j4) * (8 * 272) + ks * 32);
#pragma unroll
            for (int j4 = 0; j4 < 4; j4++) {
                mma16816(sc[2 * j4], aq[ks][0], aq[ks][1], aq[ks][2], aq[ks][3],
                         kb[4 * j4], kb[4 * j4 + 1]);
                mma16816(sc[2 * j4 + 1], aq[ks][0], aq[ks][1], aq[ks][2],
                         aq[ks][3], kb[4 * j4 + 2], kb[4 * j4 + 3]);
            }
        }

        // ---- PV with per-jp exp/pack interleaved (MUFU overlaps LDSM/MMA) ----
#pragma unroll
        for (int jp = 0; jp < 4; jp++) {
            // exp + additive mask (FFMA) + pack for this jp's 16-k slice of P
            uint32_t pp[4];
            {
                const int je = 2 * jp, jo = 2 * jp + 1;
                const float me0 = Mb[je * 8 + 2 * t];
                const float me1 = Mb[je * 8 + 2 * t + 1];
                float p0 = ex2f(fmaf(sc[je][0], KL2E, me0));
                float p1 = ex2f(fmaf(sc[je][1], KL2E, me1));
                float p2 = ex2f(fmaf(sc[je][2], KL2E, me0));
                float p3 = ex2f(fmaf(sc[je][3], KL2E, me1));
                l0 += p0 + p1;
                l1 += p2 + p3;
                pp[0] = bpack(p0, p1);
                pp[1] = bpack(p2, p3);
                const float mo0 = Mb[jo * 8 + 2 * t];
                const float mo1 = Mb[jo * 8 + 2 * t + 1];
                float q0 = ex2f(fmaf(sc[jo][0], KL2E, mo0));
                float q1 = ex2f(fmaf(sc[jo][1], KL2E, mo1));
                float q2 = ex2f(fmaf(sc[jo][2], KL2E, mo0));
                float q3 = ex2f(fmaf(sc[jo][3], KL2E, mo1));
                l0 += q0 + q1;
                l1 += q2 + q3;
                pp[2] = bpack(q0, q1);
                pp[3] = bpack(q2, q3);
            }
#pragma unroll
            for (int jg = 0; jg < 4; jg++) {
                uint32_t vbf[16];
#pragma unroll
                for (int u = 0; u < 4; u++)
                    LDSM4(vbf[4 * u], vbf[4 * u + 1], vbf[4 * u + 2],
                          vbf[4 * u + 3],
                          vfb + (jg * 8 + 2 * u) * (8 * 144) + jp * 32);
#pragma unroll
                for (int u = 0; u < 4; u++) {
                    const int jv = jg * 8 + 2 * u;
                    mma16816(oacc[jv], pp[0], pp[1], pp[2], pp[3], vbf[4 * u],
                             vbf[4 * u + 1]);
                    mma16816(oacc[jv + 1], pp[0], pp[1], pp[2], pp[3],
                             vbf[4 * u + 2], vbf[4 * u + 3]);
                }
            }
        }
    }

    // ---- epilogue: reduce l across quad lanes, apply qmask, add qv ----
    l0 += __shfl_xor_sync(0xffffffffu, l0, 1);
    l0 += __shfl_xor_sync(0xffffffffu, l0, 2);
    l1 += __shfl_xor_sync(0xffffffffu, l1, 1);
    l1 += __shfl_xor_sync(0xffffffffu, l1, 2);

    const int q0 = qbase + qw + g;
    const int vb = g_valid[b];
    const float r0 = (vb != 0 && qmask[b * NQ + q0] != 0) ? 1.f / l0 : 0.f;
    const float r1 = (vb != 0 && qmask[b * NQ + q0 + 8] != 0) ? 1.f / l1 : 0.f;

    const float* qvb = qval + (size_t)b * DVDIM * NQ;
    float* ob = out + (size_t)b * DVDIM * NQ;
#pragma unroll
    for (int jv = 0; jv < 32; jv++) {
        const int dv0 = dvbase + jv * 8 + 2 * t;
        const size_t A = (size_t)dv0 * NQ + q0;
        ob[A] = qvb[A] + oacc[jv][0] * r0;
        ob[A + NQ] = qvb[A + NQ] + oacc[jv][1] * r0;
        ob[A + 8] = qvb[A + 8] + oacc[jv][2] * r1;
        ob[A + NQ + 8] = qvb[A + NQ + 8] + oacc[jv][3] * r1;
    }
}

extern "C" void kernel_launch(void* const* d_in, const int* in_sizes, int n_in,
                              void* d_out, int out_size) {
    const float* qkey = (const float*)d_in[0];
    const float* qval = (const float*)d_in[1];
    const uint32_t* qmask = (const uint32_t*)d_in[2];
    const float* mkey = (const float*)d_in[3];
    const float* mval = (const float*)d_in[4];
    const uint32_t* mmask = (const uint32_t*)d_in[5];
    float* out = (float*)d_out;

    static bool attr_set = false;
    if (!attr_set) {
        cudaFuncSetAttribute(flash_kernel,
                             cudaFuncAttributeMaxDynamicSharedMemorySize,
                             SMEM_TOTAL);
        attr_set = true;
    }

    convk_kernel<<<dim3(NM / 32, DKDIM / 32, BATCH), 256>>>(mkey);
    convv_kernel<<<(unsigned)((size_t)BATCH * DVDIM * NM / 4 / 256), 256>>>(mval);
    valid_kernel<<<BATCH, 256>>>(qmask, mmask);
    flash_kernel<<<dim3(NQ / 128, DVDIM / 256, BATCH), 256, SMEM_TOTAL>>>(
        qkey, qval, qmask, mmask, out);
}